// round 5
// baseline (speedup 1.0000x reference)
#include <cuda_runtime.h>
#include <cstdint>

#define N_NODES 100000
#define N_EDGES 1600000
#define DIMS    128
#define N_PAD   100096               // 782 * 128 (GEMM M-tile padded)
#define NB      ((N_NODES + 1023) / 1024)   // 98 scan blocks

// ---------------- scratch (device globals: no allocation allowed) ----------
__device__ int   g_cnt[N_NODES];          // in-degree
__device__ int   g_offs[N_NODES];         // CSR offsets (exclusive scan)
__device__ int   g_cursor[N_NODES];       // scatter cursors
__device__ int   g_blocksums[NB];
__device__ int   g_sorted_src[N_EDGES];
__device__ float g_sorted_w[N_EDGES];
__device__ int   g_sorted_eid[N_EDGES];
__device__ float g_Z[(size_t)N_PAD * 256];   // [x | y] per node, fp32

// ---------------- small helpers -------------------------------------------
__device__ __forceinline__ uint32_t f2tf32(float x) {
    uint32_t o;
    asm("cvt.rna.tf32.f32 %0, %1;" : "=r"(o) : "f"(x));
    return o;
}

__device__ __forceinline__ void mma_tf32(float c[4],
    uint32_t a0, uint32_t a1, uint32_t a2, uint32_t a3,
    uint32_t b0, uint32_t b1)
{
    asm volatile(
        "mma.sync.aligned.m16n8k8.row.col.f32.tf32.tf32.f32 "
        "{%0,%1,%2,%3}, {%4,%5,%6,%7}, {%8,%9}, {%0,%1,%2,%3};\n"
        : "+f"(c[0]), "+f"(c[1]), "+f"(c[2]), "+f"(c[3])
        : "r"(a0), "r"(a1), "r"(a2), "r"(a3), "r"(b0), "r"(b1));
}

// ---------------- phase 0: zero degree counters ----------------------------
__global__ void zero_cnt_kernel() {
    int i = blockIdx.x * blockDim.x + threadIdx.x;
    if (i < N_NODES) g_cnt[i] = 0;
}

// ---------------- phase 1: histogram of dst --------------------------------
__global__ void hist_kernel(const int* __restrict__ dst) {
    int e = blockIdx.x * blockDim.x + threadIdx.x;
    if (e < N_EDGES) atomicAdd(&g_cnt[dst[e]], 1);
}

// ---------------- phase 2: exclusive scan (3 small kernels) ---------------
__global__ void scan_reduce_kernel() {       // NB blocks x 256 threads
    __shared__ int sh[256];
    int base = blockIdx.x * 1024;
    int s = 0;
    for (int i = threadIdx.x; i < 1024; i += 256) {
        int idx = base + i;
        s += (idx < N_NODES) ? g_cnt[idx] : 0;
    }
    sh[threadIdx.x] = s;
    __syncthreads();
    for (int st = 128; st > 0; st >>= 1) {
        if (threadIdx.x < st) sh[threadIdx.x] += sh[threadIdx.x + st];
        __syncthreads();
    }
    if (threadIdx.x == 0) g_blocksums[blockIdx.x] = sh[0];
}

__global__ void scan_blocksums_kernel() {    // 1 block x 128 threads
    __shared__ int sh[NB];
    if (threadIdx.x < NB) sh[threadIdx.x] = g_blocksums[threadIdx.x];
    __syncthreads();
    if (threadIdx.x == 0) {
        int run = 0;
        for (int i = 0; i < NB; ++i) { int v = sh[i]; sh[i] = run; run += v; }
    }
    __syncthreads();
    if (threadIdx.x < NB) g_blocksums[threadIdx.x] = sh[threadIdx.x];
}

__global__ void scan_final_kernel() {        // NB blocks x 1024 threads
    int i = blockIdx.x * 1024 + threadIdx.x;
    int v = (i < N_NODES) ? g_cnt[i] : 0;
    int lane = threadIdx.x & 31, w = threadIdx.x >> 5;
    int inc = v;
    #pragma unroll
    for (int d = 1; d < 32; d <<= 1) {
        int t = __shfl_up_sync(0xFFFFFFFFu, inc, d);
        if (lane >= d) inc += t;
    }
    __shared__ int ws[32];
    if (lane == 31) ws[w] = inc;
    __syncthreads();
    if (w == 0) {
        int x = ws[lane];
        #pragma unroll
        for (int d = 1; d < 32; d <<= 1) {
            int t = __shfl_up_sync(0xFFFFFFFFu, x, d);
            if (lane >= d) x += t;
        }
        ws[lane] = x;
    }
    __syncthreads();
    int excl = inc - v + (w ? ws[w - 1] : 0) + g_blocksums[blockIdx.x];
    if (i < N_NODES) { g_offs[i] = excl; g_cursor[i] = excl; }
}

// ---------------- phase 3: scatter edges into CSR order --------------------
__global__ void scatter_kernel(const int* __restrict__ src,
                               const int* __restrict__ dst,
                               const float* __restrict__ ew) {
    int e = blockIdx.x * blockDim.x + threadIdx.x;
    if (e >= N_EDGES) return;
    int d = dst[e];
    int pos = atomicAdd(&g_cursor[d], 1);
    g_sorted_src[pos] = src[e];
    g_sorted_w[pos]   = ew[e];
    g_sorted_eid[pos] = e;
}

// ---------------- phase 4: warp-per-node aggregation -----------------------
__global__ void __launch_bounds__(256) agg_kernel(
    const float* __restrict__ nfeat, const float* __restrict__ efeat)
{
    int gw   = (blockIdx.x * blockDim.x + threadIdx.x) >> 5;
    int lane = threadIdx.x & 31;
    if (gw >= N_PAD) return;

    float* zr = g_Z + (size_t)gw * 256 + lane * 4;
    if (gw >= N_NODES) {
        // pad rows: defined zeros so GEMM reads are clean & deterministic
        float4 z = make_float4(0.f, 0.f, 0.f, 0.f);
        *(float4*)zr = z;
        *(float4*)(zr + 128) = z;
        return;
    }

    const float4* nf4 = (const float4*)nfeat;
    const float4* ef4 = (const float4*)efeat;

    float4 an = make_float4(0.f, 0.f, 0.f, 0.f);
    float4 ae = make_float4(0.f, 0.f, 0.f, 0.f);

    int beg = g_offs[gw];
    int n   = g_cnt[gw];
    int end = beg + n;

    for (int j = beg; j < end; ++j) {
        int   s   = __ldg(&g_sorted_src[j]);
        float w   = __ldg(&g_sorted_w[j]);
        int   eid = __ldg(&g_sorted_eid[j]);
        float4 a = __ldg(&nf4[s * 32 + lane]);
        float4 b = __ldg(&ef4[eid * 32 + lane]);
        an.x += a.x * w; an.y += a.y * w; an.z += a.z * w; an.w += a.w * w;
        ae.x += b.x;     ae.y += b.y;     ae.z += b.z;     ae.w += b.w;
    }

    float4 self = __ldg(&nf4[gw * 32 + lane]);
    float rd1 = 1.0f / (float)(n + 1);
    float rd2 = (n > 0) ? (1.0f / (float)n) : 0.0f;

    float4 x, y;
    x.x = (an.x + 2.0f * self.x) * rd1;
    x.y = (an.y + 2.0f * self.y) * rd1;
    x.z = (an.z + 2.0f * self.z) * rd1;
    x.w = (an.w + 2.0f * self.w) * rd1;
    y.x = ae.x * rd2; y.y = ae.y * rd2; y.z = ae.z * rd2; y.w = ae.w * rd2;

    *(float4*)zr         = x;   // cols [0,128)  -> W_neigh half
    *(float4*)(zr + 128) = y;   // cols [128,256) -> W_edge half
}

// ---------------- phase 5: GEMM out = Z @ Wc^T + bias (TF32 mma) -----------
#define SSTR 36   // smem row stride (floats), multiple of 4, conflict-free

__global__ void __launch_bounds__(256) gemm_kernel(
    const float* __restrict__ Wn, const float* __restrict__ bn,
    const float* __restrict__ We, const float* __restrict__ be,
    float* __restrict__ out)
{
    __shared__ float sA[128 * SSTR];   // 18 KB
    __shared__ float sB[128 * SSTR];   // 18 KB

    int tid  = threadIdx.x;
    int warp = tid >> 5, lane = tid & 31;
    int wr = warp >> 1;        // warp row 0..3  (32 rows each)
    int wc = warp & 1;         // warp col 0..1  (64 cols each)
    int g  = lane >> 2;        // group id 0..7
    int t  = lane & 3;         // thread in group 0..3
    int blockRow = blockIdx.x * 128;

    float acc[2][8][4];
    #pragma unroll
    for (int mi = 0; mi < 2; ++mi)
        #pragma unroll
        for (int ni = 0; ni < 8; ++ni)
            #pragma unroll
            for (int c = 0; c < 4; ++c) acc[mi][ni][c] = 0.f;

    int lrow = tid >> 3;            // 0..31
    int lcol = (tid & 7) * 4;       // 0,4,...,28

    for (int kt = 0; kt < 8; ++kt) {
        const float* Bsrc = (kt < 4) ? Wn : We;
        int kofs = (kt & 3) * 32;

        // load A tile (128 x 32), convert to tf32
        #pragma unroll
        for (int i = 0; i < 4; ++i) {
            int r = lrow + i * 32;
            float4 v = *(const float4*)&g_Z[(size_t)(blockRow + r) * 256 + kt * 32 + lcol];
            float* d = &sA[r * SSTR + lcol];
            d[0] = __uint_as_float(f2tf32(v.x));
            d[1] = __uint_as_float(f2tf32(v.y));
            d[2] = __uint_as_float(f2tf32(v.z));
            d[3] = __uint_as_float(f2tf32(v.w));
        }
        // load B tile (128 outs x 32 k), convert to tf32
        #pragma unroll
        for (int i = 0; i < 4; ++i) {
            int r = lrow + i * 32;
            float4 v = *(const float4*)&Bsrc[r * 128 + kofs + lcol];
            float* d = &sB[r * SSTR + lcol];
            d[0] = __uint_as_float(f2tf32(v.x));
            d[1] = __uint_as_float(f2tf32(v.y));
            d[2] = __uint_as_float(f2tf32(v.z));
            d[3] = __uint_as_float(f2tf32(v.w));
        }
        __syncthreads();

        #pragma unroll
        for (int kk = 0; kk < 4; ++kk) {
            int kb = kk * 8;
            uint32_t bf[8][2];
            #pragma unroll
            for (int ni = 0; ni < 8; ++ni) {
                int n = wc * 64 + ni * 8 + g;
                bf[ni][0] = __float_as_uint(sB[n * SSTR + kb + t]);
                bf[ni][1] = __float_as_uint(sB[n * SSTR + kb + t + 4]);
            }
            #pragma unroll
            for (int mi = 0; mi < 2; ++mi) {
                int rb = wr * 32 + mi * 16;
                uint32_t a0 = __float_as_uint(sA[(rb + g)     * SSTR + kb + t]);
                uint32_t a1 = __float_as_uint(sA[(rb + g + 8) * SSTR + kb + t]);
                uint32_t a2 = __float_as_uint(sA[(rb + g)     * SSTR + kb + t + 4]);
                uint32_t a3 = __float_as_uint(sA[(rb + g + 8) * SSTR + kb + t + 4]);
                #pragma unroll
                for (int ni = 0; ni < 8; ++ni)
                    mma_tf32(acc[mi][ni], a0, a1, a2, a3, bf[ni][0], bf[ni][1]);
            }
        }
        __syncthreads();
    }

    // epilogue: + b_neigh + [deg>0]*b_edge ; guard M boundary
    #pragma unroll
    for (int mi = 0; mi < 2; ++mi) {
        int r0 = blockRow + wr * 32 + mi * 16 + g;
        int r1 = r0 + 8;
        bool v0 = (r0 < N_NODES), v1 = (r1 < N_NODES);
        float f0 = (v0 && g_cnt[r0] > 0) ? 1.0f : 0.0f;
        float f1 = (v1 && g_cnt[r1] > 0) ? 1.0f : 0.0f;
        #pragma unroll
        for (int ni = 0; ni < 8; ++ni) {
            int c = wc * 64 + ni * 8 + t * 2;
            float bn0 = __ldg(&bn[c]),     bn1 = __ldg(&bn[c + 1]);
            float be0 = __ldg(&be[c]),     be1 = __ldg(&be[c + 1]);
            if (v0) {
                out[(size_t)r0 * 128 + c]     = acc[mi][ni][0] + bn0 + f0 * be0;
                out[(size_t)r0 * 128 + c + 1] = acc[mi][ni][1] + bn1 + f0 * be1;
            }
            if (v1) {
                out[(size_t)r1 * 128 + c]     = acc[mi][ni][2] + bn0 + f1 * be0;
                out[(size_t)r1 * 128 + c + 1] = acc[mi][ni][3] + bn1 + f1 * be1;
            }
        }
    }
}

// ---------------- launch ----------------------------------------------------
extern "C" void kernel_launch(void* const* d_in, const int* in_sizes, int n_in,
                              void* d_out, int out_size) {
    const float* nfeat = (const float*)d_in[0];
    const float* efeat = (const float*)d_in[1];
    const float* ew    = (const float*)d_in[2];
    const float* Wn    = (const float*)d_in[3];
    const float* bn    = (const float*)d_in[4];
    const float* We    = (const float*)d_in[5];
    const float* be    = (const float*)d_in[6];
    const int*   src   = (const int*)d_in[7];
    const int*   dst   = (const int*)d_in[8];
    float* out = (float*)d_out;

    zero_cnt_kernel<<<(N_NODES + 255) / 256, 256>>>();
    hist_kernel<<<(N_EDGES + 255) / 256, 256>>>(dst);
    scan_reduce_kernel<<<NB, 256>>>();
    scan_blocksums_kernel<<<1, 128>>>();
    scan_final_kernel<<<NB, 1024>>>();
    scatter_kernel<<<(N_EDGES + 255) / 256, 256>>>(src, dst, ew);
    agg_kernel<<<N_PAD / 8, 256>>>(nfeat, efeat);
    gemm_kernel<<<N_PAD / 128, 256>>>(Wn, bn, We, be, out);
}

// round 6
// speedup vs baseline: 1.0788x; 1.0788x over previous
#include <cuda_runtime.h>
#include <cstdint>

#define N_NODES 100000
#define N_EDGES 1600000
#define DIMS    128
#define N_PAD   100096               // 782 * 128 (GEMM M-tile padded)
#define NB      ((N_NODES + 1023) / 1024)   // 98 scan blocks

// ---------------- scratch (device globals: no allocation allowed) ----------
__device__ int   g_cnt[N_NODES];          // in-degree
__device__ int   g_offs[N_NODES];         // CSR offsets (exclusive scan)
__device__ int   g_cursor[N_NODES];       // scatter cursors
__device__ int   g_blocksums[NB];
__device__ int4  g_sorted[N_EDGES];       // {src, w_bits, eid, pad} packed
__device__ float g_Z[(size_t)N_PAD * 256];   // [x | y] per node, fp32

// ---------------- small helpers -------------------------------------------
__device__ __forceinline__ uint32_t f2tf32(float x) {
    uint32_t o;
    asm("cvt.rna.tf32.f32 %0, %1;" : "=r"(o) : "f"(x));
    return o;
}

__device__ __forceinline__ void mma_tf32(float c[4],
    uint32_t a0, uint32_t a1, uint32_t a2, uint32_t a3,
    uint32_t b0, uint32_t b1)
{
    asm volatile(
        "mma.sync.aligned.m16n8k8.row.col.f32.tf32.tf32.f32 "
        "{%0,%1,%2,%3}, {%4,%5,%6,%7}, {%8,%9}, {%0,%1,%2,%3};\n"
        : "+f"(c[0]), "+f"(c[1]), "+f"(c[2]), "+f"(c[3])
        : "r"(a0), "r"(a1), "r"(a2), "r"(a3), "r"(b0), "r"(b1));
}

__device__ __forceinline__ void fma4(float4& acc, float4 v, float w) {
    acc.x += v.x * w; acc.y += v.y * w; acc.z += v.z * w; acc.w += v.w * w;
}
__device__ __forceinline__ void add4(float4& acc, float4 v) {
    acc.x += v.x; acc.y += v.y; acc.z += v.z; acc.w += v.w;
}

// ---------------- phase 0: zero degree counters ----------------------------
__global__ void zero_cnt_kernel() {
    int i = blockIdx.x * blockDim.x + threadIdx.x;
    if (i < N_NODES) g_cnt[i] = 0;
}

// ---------------- phase 1: histogram of dst (4 edges / thread) -------------
__global__ void hist_kernel(const int* __restrict__ dst) {
    int base = (blockIdx.x * blockDim.x + threadIdx.x) * 4;
    if (base >= N_EDGES) return;           // N_EDGES % 4 == 0 -> full int4 ok
    int4 d4 = *(const int4*)&dst[base];
    atomicAdd(&g_cnt[d4.x], 1);
    atomicAdd(&g_cnt[d4.y], 1);
    atomicAdd(&g_cnt[d4.z], 1);
    atomicAdd(&g_cnt[d4.w], 1);
}

// ---------------- phase 2: exclusive scan (3 small kernels) ---------------
__global__ void scan_reduce_kernel() {       // NB blocks x 256 threads
    __shared__ int sh[256];
    int base = blockIdx.x * 1024;
    int s = 0;
    for (int i = threadIdx.x; i < 1024; i += 256) {
        int idx = base + i;
        s += (idx < N_NODES) ? g_cnt[idx] : 0;
    }
    sh[threadIdx.x] = s;
    __syncthreads();
    for (int st = 128; st > 0; st >>= 1) {
        if (threadIdx.x < st) sh[threadIdx.x] += sh[threadIdx.x + st];
        __syncthreads();
    }
    if (threadIdx.x == 0) g_blocksums[blockIdx.x] = sh[0];
}

__global__ void scan_blocksums_kernel() {    // 1 block x 128 threads
    __shared__ int sh[NB];
    if (threadIdx.x < NB) sh[threadIdx.x] = g_blocksums[threadIdx.x];
    __syncthreads();
    if (threadIdx.x == 0) {
        int run = 0;
        for (int i = 0; i < NB; ++i) { int v = sh[i]; sh[i] = run; run += v; }
    }
    __syncthreads();
    if (threadIdx.x < NB) g_blocksums[threadIdx.x] = sh[threadIdx.x];
}

__global__ void scan_final_kernel() {        // NB blocks x 1024 threads
    int i = blockIdx.x * 1024 + threadIdx.x;
    int v = (i < N_NODES) ? g_cnt[i] : 0;
    int lane = threadIdx.x & 31, w = threadIdx.x >> 5;
    int inc = v;
    #pragma unroll
    for (int d = 1; d < 32; d <<= 1) {
        int t = __shfl_up_sync(0xFFFFFFFFu, inc, d);
        if (lane >= d) inc += t;
    }
    __shared__ int ws[32];
    if (lane == 31) ws[w] = inc;
    __syncthreads();
    if (w == 0) {
        int x = ws[lane];
        #pragma unroll
        for (int d = 1; d < 32; d <<= 1) {
            int t = __shfl_up_sync(0xFFFFFFFFu, x, d);
            if (lane >= d) x += t;
        }
        ws[lane] = x;
    }
    __syncthreads();
    int excl = inc - v + (w ? ws[w - 1] : 0) + g_blocksums[blockIdx.x];
    if (i < N_NODES) { g_offs[i] = excl; g_cursor[i] = excl; }
}

// ---------------- phase 3: scatter edges into CSR order (packed int4) ------
__global__ void scatter_kernel(const int* __restrict__ src,
                               const int* __restrict__ dst,
                               const float* __restrict__ ew) {
    int base = (blockIdx.x * blockDim.x + threadIdx.x) * 4;
    if (base >= N_EDGES) return;
    int4   s4 = *(const int4*)&src[base];
    int4   d4 = *(const int4*)&dst[base];
    float4 w4 = *(const float4*)&ew[base];

    int p0 = atomicAdd(&g_cursor[d4.x], 1);
    g_sorted[p0] = make_int4(s4.x, __float_as_int(w4.x), base + 0, 0);
    int p1 = atomicAdd(&g_cursor[d4.y], 1);
    g_sorted[p1] = make_int4(s4.y, __float_as_int(w4.y), base + 1, 0);
    int p2 = atomicAdd(&g_cursor[d4.z], 1);
    g_sorted[p2] = make_int4(s4.z, __float_as_int(w4.z), base + 2, 0);
    int p3 = atomicAdd(&g_cursor[d4.w], 1);
    g_sorted[p3] = make_int4(s4.w, __float_as_int(w4.w), base + 3, 0);
}

// ---------------- phase 4: warp-per-node aggregation -----------------------
__global__ void __launch_bounds__(256) agg_kernel(
    const float* __restrict__ nfeat, const float* __restrict__ efeat)
{
    int gw   = (blockIdx.x * blockDim.x + threadIdx.x) >> 5;
    int lane = threadIdx.x & 31;
    if (gw >= N_PAD) return;

    float* zr = g_Z + (size_t)gw * 256 + lane * 4;
    if (gw >= N_NODES) {
        float4 z = make_float4(0.f, 0.f, 0.f, 0.f);
        __stcs((float4*)zr, z);
        __stcs((float4*)(zr + 128), z);
        return;
    }

    const float4* nf4 = (const float4*)nfeat;
    const float4* ef4 = (const float4*)efeat;

    float4 an = make_float4(0.f, 0.f, 0.f, 0.f);
    float4 ae = make_float4(0.f, 0.f, 0.f, 0.f);

    int beg = g_offs[gw];
    int n   = g_cnt[gw];
    int end = beg + n;
    int j   = beg;

    // unroll x4: front-batched independent loads for MLP
    for (; j + 4 <= end; j += 4) {
        int4 p0 = __ldg(&g_sorted[j]);
        int4 p1 = __ldg(&g_sorted[j + 1]);
        int4 p2 = __ldg(&g_sorted[j + 2]);
        int4 p3 = __ldg(&g_sorted[j + 3]);
        float4 a0 = __ldg(&nf4[(size_t)p0.x * 32 + lane]);
        float4 a1 = __ldg(&nf4[(size_t)p1.x * 32 + lane]);
        float4 a2 = __ldg(&nf4[(size_t)p2.x * 32 + lane]);
        float4 a3 = __ldg(&nf4[(size_t)p3.x * 32 + lane]);
        float4 e0 = __ldcs(&ef4[(size_t)p0.z * 32 + lane]);
        float4 e1 = __ldcs(&ef4[(size_t)p1.z * 32 + lane]);
        float4 e2 = __ldcs(&ef4[(size_t)p2.z * 32 + lane]);
        float4 e3 = __ldcs(&ef4[(size_t)p3.z * 32 + lane]);
        fma4(an, a0, __int_as_float(p0.y));
        fma4(an, a1, __int_as_float(p1.y));
        fma4(an, a2, __int_as_float(p2.y));
        fma4(an, a3, __int_as_float(p3.y));
        add4(ae, e0); add4(ae, e1); add4(ae, e2); add4(ae, e3);
    }
    for (; j < end; ++j) {
        int4 p = __ldg(&g_sorted[j]);
        float4 a = __ldg(&nf4[(size_t)p.x * 32 + lane]);
        float4 e = __ldcs(&ef4[(size_t)p.z * 32 + lane]);
        fma4(an, a, __int_as_float(p.y));
        add4(ae, e);
    }

    float4 self = __ldg(&nf4[(size_t)gw * 32 + lane]);
    float rd1 = 1.0f / (float)(n + 1);
    float rd2 = (n > 0) ? (1.0f / (float)n) : 0.0f;

    float4 x, y;
    x.x = (an.x + 2.0f * self.x) * rd1;
    x.y = (an.y + 2.0f * self.y) * rd1;
    x.z = (an.z + 2.0f * self.z) * rd1;
    x.w = (an.w + 2.0f * self.w) * rd1;
    y.x = ae.x * rd2; y.y = ae.y * rd2; y.z = ae.z * rd2; y.w = ae.w * rd2;

    __stcs((float4*)zr, x);          // cols [0,128)   -> W_neigh half
    __stcs((float4*)(zr + 128), y);  // cols [128,256) -> W_edge half
}

// ---------------- phase 5: GEMM out = Z @ Wc^T + bias (TF32 mma) -----------
#define SSTR 36   // smem row stride (floats), multiple of 4, conflict-free

__global__ void __launch_bounds__(256) gemm_kernel(
    const float* __restrict__ Wn, const float* __restrict__ bn,
    const float* __restrict__ We, const float* __restrict__ be,
    float* __restrict__ out)
{
    __shared__ float sA[128 * SSTR];   // 18 KB
    __shared__ float sB[128 * SSTR];   // 18 KB

    int tid  = threadIdx.x;
    int warp = tid >> 5, lane = tid & 31;
    int wr = warp >> 1;        // warp row 0..3  (32 rows each)
    int wc = warp & 1;         // warp col 0..1  (64 cols each)
    int g  = lane >> 2;        // group id 0..7
    int t  = lane & 3;         // thread in group 0..3
    int blockRow = blockIdx.x * 128;

    float acc[2][8][4];
    #pragma unroll
    for (int mi = 0; mi < 2; ++mi)
        #pragma unroll
        for (int ni = 0; ni < 8; ++ni)
            #pragma unroll
            for (int c = 0; c < 4; ++c) acc[mi][ni][c] = 0.f;

    int lrow = tid >> 3;            // 0..31
    int lcol = (tid & 7) * 4;       // 0,4,...,28

    for (int kt = 0; kt < 8; ++kt) {
        const float* Bsrc = (kt < 4) ? Wn : We;
        int kofs = (kt & 3) * 32;

        // load A tile (128 x 32), convert to tf32
        #pragma unroll
        for (int i = 0; i < 4; ++i) {
            int r = lrow + i * 32;
            float4 v = __ldcs((const float4*)&g_Z[(size_t)(blockRow + r) * 256 + kt * 32 + lcol]);
            float* d = &sA[r * SSTR + lcol];
            d[0] = __uint_as_float(f2tf32(v.x));
            d[1] = __uint_as_float(f2tf32(v.y));
            d[2] = __uint_as_float(f2tf32(v.z));
            d[3] = __uint_as_float(f2tf32(v.w));
        }
        // load B tile (128 outs x 32 k), convert to tf32
        #pragma unroll
        for (int i = 0; i < 4; ++i) {
            int r = lrow + i * 32;
            float4 v = *(const float4*)&Bsrc[r * 128 + kofs + lcol];
            float* d = &sB[r * SSTR + lcol];
            d[0] = __uint_as_float(f2tf32(v.x));
            d[1] = __uint_as_float(f2tf32(v.y));
            d[2] = __uint_as_float(f2tf32(v.z));
            d[3] = __uint_as_float(f2tf32(v.w));
        }
        __syncthreads();

        #pragma unroll
        for (int kk = 0; kk < 4; ++kk) {
            int kb = kk * 8;
            uint32_t bf[8][2];
            #pragma unroll
            for (int ni = 0; ni < 8; ++ni) {
                int n = wc * 64 + ni * 8 + g;
                bf[ni][0] = __float_as_uint(sB[n * SSTR + kb + t]);
                bf[ni][1] = __float_as_uint(sB[n * SSTR + kb + t + 4]);
            }
            #pragma unroll
            for (int mi = 0; mi < 2; ++mi) {
                int rb = wr * 32 + mi * 16;
                uint32_t a0 = __float_as_uint(sA[(rb + g)     * SSTR + kb + t]);
                uint32_t a1 = __float_as_uint(sA[(rb + g + 8) * SSTR + kb + t]);
                uint32_t a2 = __float_as_uint(sA[(rb + g)     * SSTR + kb + t + 4]);
                uint32_t a3 = __float_as_uint(sA[(rb + g + 8) * SSTR + kb + t + 4]);
                #pragma unroll
                for (int ni = 0; ni < 8; ++ni)
                    mma_tf32(acc[mi][ni], a0, a1, a2, a3, bf[ni][0], bf[ni][1]);
            }
        }
        __syncthreads();
    }

    // epilogue: + b_neigh + [deg>0]*b_edge ; guard M boundary
    #pragma unroll
    for (int mi = 0; mi < 2; ++mi) {
        int r0 = blockRow + wr * 32 + mi * 16 + g;
        int r1 = r0 + 8;
        bool v0 = (r0 < N_NODES), v1 = (r1 < N_NODES);
        float f0 = (v0 && g_cnt[r0] > 0) ? 1.0f : 0.0f;
        float f1 = (v1 && g_cnt[r1] > 0) ? 1.0f : 0.0f;
        #pragma unroll
        for (int ni = 0; ni < 8; ++ni) {
            int c = wc * 64 + ni * 8 + t * 2;
            float bn0 = __ldg(&bn[c]),     bn1 = __ldg(&bn[c + 1]);
            float be0 = __ldg(&be[c]),     be1 = __ldg(&be[c + 1]);
            if (v0) {
                out[(size_t)r0 * 128 + c]     = acc[mi][ni][0] + bn0 + f0 * be0;
                out[(size_t)r0 * 128 + c + 1] = acc[mi][ni][1] + bn1 + f0 * be1;
            }
            if (v1) {
                out[(size_t)r1 * 128 + c]     = acc[mi][ni][2] + bn0 + f1 * be0;
                out[(size_t)r1 * 128 + c + 1] = acc[mi][ni][3] + bn1 + f1 * be1;
            }
        }
    }
}

// ---------------- launch ----------------------------------------------------
extern "C" void kernel_launch(void* const* d_in, const int* in_sizes, int n_in,
                              void* d_out, int out_size) {
    const float* nfeat = (const float*)d_in[0];
    const float* efeat = (const float*)d_in[1];
    const float* ew    = (const float*)d_in[2];
    const float* Wn    = (const float*)d_in[3];
    const float* bn    = (const float*)d_in[4];
    const float* We    = (const float*)d_in[5];
    const float* be    = (const float*)d_in[6];
    const int*   src   = (const int*)d_in[7];
    const int*   dst   = (const int*)d_in[8];
    float* out = (float*)d_out;

    zero_cnt_kernel<<<(N_NODES + 255) / 256, 256>>>();
    hist_kernel<<<(N_EDGES / 4 + 255) / 256, 256>>>(dst);
    scan_reduce_kernel<<<NB, 256>>>();
    scan_blocksums_kernel<<<1, 128>>>();
    scan_final_kernel<<<NB, 1024>>>();
    scatter_kernel<<<(N_EDGES / 4 + 255) / 256, 256>>>(src, dst, ew);
    agg_kernel<<<N_PAD / 8, 256>>>(nfeat, efeat);
    gemm_kernel<<<N_PAD / 128, 256>>>(Wn, bn, We, be, out);
}